// round 1
// baseline (speedup 1.0000x reference)
#include <cuda_runtime.h>

// AEC frequency-domain dual-filter IPNLMS.
// Serial scan over T*B = 16000 frames; F=129 independent bins -> 1 thread/bin,
// all state in registers. 5 blocks x 32 threads (one warp per SM).

namespace {
constexpr int F_BINS = 129;
constexpr int K = 10;
constexpr int BATCH = 8;
constexpr int T_FRAMES = 2000;
constexpr int NF = BATCH * T_FRAMES;        // 16000 serial frames
constexpr float LAM = 0.97f;
constexpr float ONE_M_LAM = (float)(1.0 - 0.97);   // match python-double-derived constant
}

__global__ void __launch_bounds__(32, 1)
aec_ipnlms_kernel(const float* __restrict__ mic_r, const float* __restrict__ mic_i,
                  const float* __restrict__ ref_r, const float* __restrict__ ref_i,
                  const float* __restrict__ fir_r0, const float* __restrict__ fir_i0,
                  const float* __restrict__ adf_r0, const float* __restrict__ adf_i0,
                  float2* __restrict__ out)
{
    const int gid = blockIdx.x * 32 + threadIdx.x;
    const bool active = gid < F_BINS;
    const int f = active ? gid : (F_BINS - 1);   // inactive lanes shadow bin 128 (no store)
    const bool low = (f <= 35);                  // rows < AEC_MID_CHAN+1 -> K_LOW=10 taps
    const float m89 = low ? 1.0f : 0.0f;         // mask for taps 8,9
    const float c0  = low ? (0.25f / 10.0f) : (0.25f / 8.0f);  // (1-ALPHA)/(2*nblocks)

    // ---- register-resident state ----
    float hr[K], hi[K], fr_[K], fi_[K], ar_[K], ai_[K];
#pragma unroll
    for (int k = 0; k < K; ++k) {
        const float mk = (k < 8) ? 1.0f : m89;   // zero masked taps: provably output-equivalent
        hr[k] = 0.0f; hi[k] = 0.0f;
        fr_[k] = fir_r0[f * K + k] * mk;
        fi_[k] = fir_i0[f * K + k] * mk;
        ar_[k] = adf_r0[f * K + k] * mk;
        ai_[k] = adf_i0[f * K + k] * mk;
    }
    float mse_in = 1.0f, mse_adpt = 1.0f, mse_main = 1.0f;

    // ---- 2-deep input prefetch pipeline (ping-pong registers) ----
    float pm_r[2], pm_i[2], pq_r[2], pq_i[2];
    {
        // frame 0: (t=0,b=0) off=f ; frame 1: (t=0,b=1) off=T*F+f
        pm_r[0] = mic_r[f];              pm_i[0] = mic_i[f];
        pq_r[0] = ref_r[f];              pq_i[0] = ref_i[f];
        const int o1 = T_FRAMES * F_BINS + f;
        pm_r[1] = mic_r[o1];             pm_i[1] = mic_i[o1];
        pq_r[1] = ref_r[o1];             pq_i[1] = ref_i[o1];
    }

    int nlp_cnt = 0;  // n % NLP_INTERVAL

#pragma unroll 2
    for (int n = 0; n < NF; ++n) {
        const int slot = n & 1;
        const float mr_f = pm_r[slot], mi_f = pm_i[slot];
        const float rr_f = pq_r[slot], ri_f = pq_i[slot];

        // prefetch frame n+2 into the slot we just consumed
        const int n2 = n + 2;
        if (n2 < NF) {
            const int b2 = n2 & 7, t2 = n2 >> 3;
            const int off = b2 * (T_FRAMES * F_BINS) + t2 * F_BINS + f;
            pm_r[slot] = __ldg(mic_r + off);
            pm_i[slot] = __ldg(mic_i + off);
            pq_r[slot] = __ldg(ref_r + off);
            pq_i[slot] = __ldg(ref_i + off);
        }

        // ---- history shift-in ----
#pragma unroll
        for (int k = K - 1; k > 0; --k) { hr[k] = hr[k - 1]; hi[k] = hi[k - 1]; }
        hr[0] = rr_f; hi[0] = ri_f;

        // ---- dual-filter echo estimates (mask pre-folded into coefs) ----
        float fer = 0.f, fei = 0.f, aer = 0.f, aei = 0.f;
#pragma unroll
        for (int k = 0; k < K; ++k) {
            fer += fr_[k] * hr[k] + fi_[k] * hi[k];
            fei += fr_[k] * hi[k] - fi_[k] * hr[k];
            aer += ar_[k] * hr[k] + ai_[k] * hi[k];
            aei += ar_[k] * hi[k] - ai_[k] * hr[k];
        }
        const float fe_r = mr_f - fer, fe_i = mi_f - fei;
        const float ae_r = mr_f - aer, ae_i = mi_f - aei;
        const float f_pow = fe_r * fe_r + fe_i * fe_i;
        const float a_pow = ae_r * ae_r + ae_i * ae_i;
        const bool selA = (f_pow >= a_pow);
        const float err_r = selA ? ae_r : fe_r;
        const float err_i = selA ? ae_i : fe_i;
        const float ech_r = selA ? aer : fer;
        const float ech_i = selA ? aei : fei;

        // ---- MSE smoothing + control flags ----
        mse_in   = LAM * mse_in   + ONE_M_LAM * (mr_f * mr_f + mi_f * mi_f);
        mse_main = LAM * mse_main + ONE_M_LAM * f_pow;
        mse_adpt = LAM * mse_adpt + ONE_M_LAM * a_pow;
        const float gate = (mse_adpt > mse_in * 8.0f) ? 0.0f : 1.0f;  // 1 - double-talk
        const bool rec = (mse_in > mse_main * 8.0f) && (mse_main < 0.5f * mse_adpt);

        // ---- IPNLMS update of adaptive filter ----
        float s = 1e-10f;
        float mag2[K];
#pragma unroll
        for (int k = 0; k < K; ++k) { mag2[k] = ar_[k] * ar_[k] + ai_[k] * ai_[k]; s += mag2[k]; }
        const float inv_s = 1.0f / s;
        float tot = 0.f;
#pragma unroll
        for (int k = 0; k < 8; ++k) tot += hr[k] * hr[k] + hi[k] * hi[k];
        tot += m89 * (hr[8] * hr[8] + hi[8] * hi[8] + hr[9] * hr[9] + hi[9] * hi[9]);
        const float mu_n = 0.5f / ((tot + 1e-8f) + 1e-10f);
        const float mug = mu_n * gate;                 // gate in {0,1}: folds through clip
        float m2max = 0.f;
#pragma unroll
        for (int k = 0; k < K; ++k) {
            const float mk = (k < 8) ? 1.0f : m89;     // mask in {0,1}: folds through clip
            const float kl = (c0 + 1.5f * mag2[k] * inv_s) * mk;
            const float g2 = mug * kl;
            const float p_r = hr[k] * ae_r + hi[k] * ae_i;
            const float p_i = hi[k] * ae_r - hr[k] * ae_i;
            const float u_r = fminf(fmaxf(g2 * p_r, -0.01f), 0.01f);
            const float u_i = fminf(fmaxf(g2 * p_i, -0.01f), 0.01f);
            ar_[k] += u_r; ai_[k] += u_i;
            m2max = fmaxf(m2max, ar_[k] * ar_[k] + ai_[k] * ai_[k]);
        }
        // MAX_COEF renorm: rare; keep 10x(sqrt+div) off the common path
        if (__any_sync(0xffffffffu, m2max >= 4.0f)) {
#pragma unroll
            for (int k = 0; k < K; ++k) {
                const float m2 = ar_[k] * ar_[k] + ai_[k] * ai_[k] + 1e-10f;
                const float mg = sqrtf(m2);
                const float sc = (mg > 2.0f) ? (2.0f / mg) : 1.0f;
                ar_[k] *= sc; ai_[k] *= sc;
            }
        }

        // ---- copy adaptive -> main where adaptive won, then recovery ----
#pragma unroll
        for (int k = 0; k < K; ++k) {
            fr_[k] = selA ? ar_[k] : fr_[k];
            fi_[k] = selA ? ai_[k] : fi_[k];
        }
#pragma unroll
        for (int k = 0; k < K; ++k) {
            ar_[k] = rec ? fr_[k] : ar_[k];
            ai_[k] = rec ? fi_[k] : ai_[k];
        }

        // ---- periodic spectral-subtraction NLP (uniform branch) ----
        float o_r = err_r, o_i = err_i;
        if (nlp_cnt == 0) {
            const float em = sqrtf(err_r * err_r + err_i * err_i + 1e-12f);
            const float cm = sqrtf(ech_r * ech_r + ech_i * ech_i);
            const float supp = fmaxf(em - 1.5f * cm, 0.01f * em);
            const float g = supp / em;
            o_r = g * err_r; o_i = g * err_i;
        }
        nlp_cnt = (nlp_cnt == 9) ? 0 : (nlp_cnt + 1);

        if (active) {
            const int b = n & 7, t = n >> 3;
            out[(b * T_FRAMES + t) * F_BINS + f] = make_float2(o_r, o_i);
        }
    }
}

extern "C" void kernel_launch(void* const* d_in, const int* in_sizes, int n_in,
                              void* d_out, int out_size) {
    (void)in_sizes; (void)n_in; (void)out_size;
    aec_ipnlms_kernel<<<5, 32>>>(
        (const float*)d_in[0], (const float*)d_in[1],
        (const float*)d_in[2], (const float*)d_in[3],
        (const float*)d_in[4], (const float*)d_in[5],
        (const float*)d_in[6], (const float*)d_in[7],
        (float2*)d_out);
}

// round 2
// speedup vs baseline: 1.0845x; 1.0845x over previous
#include <cuda_runtime.h>

// AEC frequency-domain dual-filter IPNLMS, round 2.
// 16000 serial frames; 129 independent bins; 2 lanes per bin (taps split 5+5),
// pair reductions via SHFL.XOR. Frame loop unrolled x10: history rotation is
// static register renaming, NLP branch is compile-time. 9 blocks x 32 threads
// (one warp per SM for max per-warp issue bandwidth).

namespace {
constexpr int F_BINS   = 129;
constexpr int T_FRAMES = 2000;
constexpr int NF       = 16000;          // B*T, serial order (t, b)
constexpr int TF       = T_FRAMES * F_BINS;
}

__device__ __forceinline__ float pair_sum(float v) {
    return v + __shfl_xor_sync(0xffffffffu, v, 1);
}

__global__ void __launch_bounds__(32, 1)
aec_ipnlms2(const float* __restrict__ mic_r, const float* __restrict__ mic_i,
            const float* __restrict__ ref_r, const float* __restrict__ ref_i,
            const float* __restrict__ fir_r0, const float* __restrict__ fir_i0,
            const float* __restrict__ adf_r0, const float* __restrict__ adf_i0,
            float2* __restrict__ out)
{
    const float LAM = 0.97f;
    const float OML = (float)(1.0 - 0.97);   // match python double-derived constant

    const int lane = threadIdx.x;
    const int gid  = blockIdx.x * 32 + lane;
    const int bin  = gid >> 1;
    const int half = gid & 1;                 // 0: taps 0-4, 1: taps 5-9
    const bool writer = (half == 0) && (bin < F_BINS);
    const int f = (bin < F_BINS) ? bin : (F_BINS - 1);   // shadow lanes track bin 128
    const bool low = (f <= 35);               // K_LOW=10 taps, else K_HIGH=8
    const float m89   = low ? 1.0f : 0.0f;    // mask for global taps 8,9
    const float c0    = low ? 0.025f : 0.03125f;   // (1-ALPHA)/(2*nblocks)
    const float mtail = half ? m89 : 1.0f;    // mask applying to this lane's taps j=3,4

    // ---- register state: 5 taps per lane ----
    float Hr[5], Hi[5], cfr[5], cfi[5], car[5], cai[5], mg2[5];
    float s_loc = 0.0f;
#pragma unroll
    for (int j = 0; j < 5; ++j) {
        const int k = half * 5 + j;
        const float mk = (k < 8) ? 1.0f : m89;  // zero masked taps (output-equivalent)
        Hr[j] = 0.0f; Hi[j] = 0.0f;
        cfr[j] = fir_r0[f * 10 + k] * mk;  cfi[j] = fir_i0[f * 10 + k] * mk;
        car[j] = adf_r0[f * 10 + k] * mk;  cai[j] = adf_i0[f * 10 + k] * mk;
        mg2[j] = car[j] * car[j] + cai[j] * cai[j];
        s_loc += mg2[j];
    }
    float s_sum = pair_sum(s_loc);            // carried Σ|a|^2 (pre-1e-10)
    float mse_in = 1.0f, mse_ad = 1.0f, mse_mn = 1.0f;

    // ---- 2-deep prefetch pipeline (data + offsets, ping-pong) ----
    float pmr[2], pmi[2], prr[2], pri[2];
    int poff[2] = { f, TF + f };              // off(n) = b*T*F + t*F + f, n in (t,b) order
    pmr[0] = mic_r[poff[0]]; pmi[0] = mic_i[poff[0]];
    prr[0] = ref_r[poff[0]]; pri[0] = ref_i[poff[0]];
    pmr[1] = mic_r[poff[1]]; pmi[1] = mic_i[poff[1]];
    prr[1] = ref_r[poff[1]]; pri[1] = ref_i[poff[1]];

    for (int n0 = 0; n0 < NF; n0 += 10) {
#pragma unroll
        for (int u = 0; u < 10; ++u) {        // fully unrolled: u is compile-time
            const int n  = n0 + u;
            const int sl = u & 1;
            const float mr_f = pmr[sl], mi_f = pmi[sl];
            const float rr_f = prr[sl], ri_f = pri[sl];
            const int ooff = poff[sl];        // read before overwrite

            // prefetch frame n+2
            {
                const int n2 = n + 2;
                if (n2 < NF) {
                    const int off = (n2 & 7) * TF + (n2 >> 3) * F_BINS + f;
                    poff[sl] = off;
                    pmr[sl] = __ldg(mic_r + off); pmi[sl] = __ldg(mic_i + off);
                    prr[sl] = __ldg(ref_r + off); pri[sl] = __ldg(ref_i + off);
                }
            }

            // ---- history rotation (no MOVs): tap j lives in slot (j-u) mod 5.
            // Incoming tap0 -> slot ins; lane1's tap5 = lane0's outgoing slot value.
            const int ins = (10 - u) % 5;
            const float xr = __shfl_xor_sync(0xffffffffu, Hr[ins], 1);
            const float xi = __shfl_xor_sync(0xffffffffu, Hi[ins], 1);
            Hr[ins] = half ? xr : rr_f;
            Hi[ins] = half ? xi : ri_f;

            // ---- dual-filter echo estimates (lane-partial, then pair-reduce) ----
            float fer = 0.f, fei = 0.f, aer = 0.f, aei = 0.f;
#pragma unroll
            for (int j = 0; j < 5; ++j) {
                const int p = ((j - u) % 5 + 5) % 5;
                const float hr = Hr[p], hi = Hi[p];
                fer += cfr[j] * hr + cfi[j] * hi;
                fei += cfr[j] * hi - cfi[j] * hr;
                aer += car[j] * hr + cai[j] * hi;
                aei += car[j] * hi - cai[j] * hr;
            }
            fer = pair_sum(fer); fei = pair_sum(fei);
            aer = pair_sum(aer); aei = pair_sum(aei);

            const float feR = mr_f - fer, feI = mi_f - fei;
            const float aeR = mr_f - aer, aeI = mi_f - aei;
            const float f_pow = feR * feR + feI * feI;
            const float a_pow = aeR * aeR + aeI * aeI;
            const bool selA = (f_pow >= a_pow);
            const float errR = selA ? aeR : feR;
            const float errI = selA ? aeI : feI;

            // ---- MSE smoothing + control flags ----
            mse_in = LAM * mse_in + OML * (mr_f * mr_f + mi_f * mi_f);
            mse_mn = LAM * mse_mn + OML * f_pow;
            mse_ad = LAM * mse_ad + OML * a_pow;
            const float gate = (mse_ad > mse_in * 8.0f) ? 0.0f : 1.0f;
            const bool rec = (mse_in > mse_mn * 8.0f) && (mse_mn < 0.5f * mse_ad);

            // ---- masked reference power (sliding window, exact) ----
            float tl = 0.f, tt = 0.f;
#pragma unroll
            for (int j = 0; j < 5; ++j) {
                const int p = ((j - u) % 5 + 5) % 5;
                const float v = Hr[p] * Hr[p] + Hi[p] * Hi[p];
                if (j < 3) tl += v; else tt += v;
            }
            tl += mtail * tt;
            const float tot  = pair_sum(tl);
            const float mu_n = __fdividef(0.5f, (tot + 1e-8f) + 1e-10f);
            const float mug  = mu_n * gate;                       // gate folds through clip
            const float invs15 = __fdividef(1.5f, s_sum + 1e-10f);
            const float A = mug * c0;
            const float B = mug * invs15;

            // ---- IPNLMS update (mask folds through clip; mg2 doubles as next s) ----
            float s_new = 0.f;
#pragma unroll
            for (int j = 0; j < 5; ++j) {
                const int p = ((j - u) % 5 + 5) % 5;
                const float hr = Hr[p], hi = Hi[p];
                float g2 = A + mg2[j] * B;                        // mug * kl
                if (j >= 3) g2 *= mtail;
                const float p_r = hr * aeR + hi * aeI;
                const float p_i = hi * aeR - hr * aeI;
                const float ur = fminf(fmaxf(g2 * p_r, -0.01f), 0.01f);
                const float ui = fminf(fmaxf(g2 * p_i, -0.01f), 0.01f);
                car[j] += ur; cai[j] += ui;
                mg2[j] = car[j] * car[j] + cai[j] * cai[j];
                s_new += mg2[j];
            }
            float s_tot = pair_sum(s_new);

            // ---- MAX_COEF renorm: s_tot < 4 => every scale is exactly 1 (skip) ----
            if (__any_sync(0xffffffffu, s_tot >= 4.0f)) {
#pragma unroll
                for (int j = 0; j < 5; ++j) {
                    const float mgv = sqrtf(mg2[j] + 1e-10f);
                    const float sc = (mgv > 2.0f) ? (2.0f / mgv) : 1.0f;
                    car[j] *= sc; cai[j] *= sc;
                    mg2[j] = car[j] * car[j] + cai[j] * cai[j];
                }
                float s2 = mg2[0] + mg2[1] + mg2[2] + mg2[3] + mg2[4];
                s_tot = pair_sum(s2);
            }

            // ---- copy adaptive -> main where adaptive won ----
#pragma unroll
            for (int j = 0; j < 5; ++j) {
                cfr[j] = selA ? car[j] : cfr[j];
                cfi[j] = selA ? cai[j] : cfi[j];
            }
            // ---- recovery (rare): reload adaptive from main; fix carried mg2/s ----
            if (__any_sync(0xffffffffu, rec)) {
                float s2 = 0.f;
#pragma unroll
                for (int j = 0; j < 5; ++j) {
                    car[j] = rec ? cfr[j] : car[j];
                    cai[j] = rec ? cfi[j] : cai[j];
                    mg2[j] = car[j] * car[j] + cai[j] * cai[j];
                    s2 += mg2[j];
                }
                s_tot = pair_sum(s2);
            }
            s_sum = s_tot;

            // ---- NLP every 10th frame (compile-time slot) ----
            float o_r = errR, o_i = errI;
            if (u == 0) {
                const float echR = selA ? aer : fer;
                const float echI = selA ? aei : fei;
                const float em = sqrtf(errR * errR + errI * errI + 1e-12f);
                const float cm = sqrtf(echR * echR + echI * echI);
                const float supp = fmaxf(em - 1.5f * cm, 0.01f * em);
                const float g = supp / em;
                o_r = g * errR; o_i = g * errI;
            }

            if (writer) out[ooff] = make_float2(o_r, o_i);
        }
    }
}

extern "C" void kernel_launch(void* const* d_in, const int* in_sizes, int n_in,
                              void* d_out, int out_size) {
    (void)in_sizes; (void)n_in; (void)out_size;
    aec_ipnlms2<<<9, 32>>>(
        (const float*)d_in[0], (const float*)d_in[1],
        (const float*)d_in[2], (const float*)d_in[3],
        (const float*)d_in[4], (const float*)d_in[5],
        (const float*)d_in[6], (const float*)d_in[7],
        (float2*)d_out);
}